// round 4
// baseline (speedup 1.0000x reference)
#include <cuda_runtime.h>

// Problem constants
#define SHIFT   4
#define HEADS   4
#define HDIM    32
#define MTOK    128      // tokens per window (8*8*2)
#define NR      225      // distinct rel-pos indices (15*15)
#define QS      36       // padded row stride (floats) for q/k/v/embed tiles
#define AS      130      // padded row stride (floats) for attn matrix (even -> pair-aligned float2)
#define SCALE   0.17677669529663687f   // 32^-0.5

// shared memory layout (in floats)
#define SQ_OFF   0
#define SK_OFF   (MTOK*QS)
#define SV_OFF   (2*MTOK*QS)
#define SQE_OFF  (3*MTOK*QS)
#define SKE_OFF  (SQE_OFF + NR*QS)
#define SVE_OFF  (SKE_OFF + NR*QS)
#define SA_OFF   (SVE_OFF + NR*QS)
#define SMEM_FLOATS (SA_OFF + MTOK*AS)   // 54,764 floats = 219,056 bytes

__global__ __launch_bounds__(256, 1)
void swin_attn_kernel(const float* __restrict__ qkv,
                      const float* __restrict__ mask,
                      const float* __restrict__ rpe,
                      float* __restrict__ out)
{
    extern __shared__ float sm[];
    float* sQ  = sm + SQ_OFF;
    float* sK  = sm + SK_OFF;
    float* sV  = sm + SV_OFF;
    float* sQE = sm + SQE_OFF;   // q_embed slice (pre-scaled)
    float* sKE = sm + SKE_OFF;   // k_embed slice
    float* sVE = sm + SVE_OFF;   // v_embed slice
    float* sA  = sm + SA_OFF;    // attn [128][130]

    const int tid = threadIdx.x;
    const int h   = blockIdx.y;
    const int b   = blockIdx.x >> 8;
    const int win = blockIdx.x & 255;
    const int wi  = win >> 4;
    const int wj  = win & 15;

    // ---- load q,k,v tokens (2 threads per token, 16 floats each) ----
    {
        const int t = tid >> 1, half = tid & 1;
        const int wh = t >> 4, ww = (t >> 1) & 7, n = t & 1;
        const int gy = (wi*8 + wh + SHIFT) & 127;
        const int gx = (wj*8 + ww + SHIFT) & 127;
        const float* base = qkv + (size_t)((((b*128 + gy)*128 + gx)*2 + n)*384) + h*32 + half*16;
        #pragma unroll
        for (int c4 = 0; c4 < 4; c4++) {
            float4 q = ((const float4*)base)[c4];
            float4 k = ((const float4*)(base + 128))[c4];
            float4 v = ((const float4*)(base + 256))[c4];
            q.x *= SCALE; q.y *= SCALE; q.z *= SCALE; q.w *= SCALE;
            *(float4*)(sQ + t*QS + half*16 + c4*4) = q;
            *(float4*)(sK + t*QS + half*16 + c4*4) = k;
            *(float4*)(sV + t*QS + half*16 + c4*4) = v;
        }
    }

    // ---- load 225 rel-pos table rows (q/k/v slices for this head) ----
    // rpe_table row layout is HEAD-MAJOR: [head][q(32)|k(32)|v(32)]
    for (int idx = tid; idx < NR*24; idx += 256) {
        const int r  = idx / 24;
        const int s  = idx % 24;
        const int sl = s >> 3;          // 0=q_embed, 1=k_embed, 2=v_embed
        const int c4 = s & 7;
        float4 v = *(const float4*)(rpe + (size_t)r*384 + h*96 + sl*32 + c4*4);
        float* dst = (sl == 0) ? sQE : (sl == 1) ? sKE : sVE;
        if (sl == 0) { v.x *= SCALE; v.y *= SCALE; v.z *= SCALE; v.w *= SCALE; }
        *(float4*)(dst + r*QS + c4*4) = v;
    }
    __syncthreads();

    // ---- pass 1: qk GEMM (+mask) -> sA, 8x8 register tile per thread ----
    {
        const int ti = tid >> 4, tj = tid & 15;
        float acc[8][8];
        #pragma unroll
        for (int a = 0; a < 8; a++)
            #pragma unroll
            for (int c = 0; c < 8; c++) acc[a][c] = 0.f;

        #pragma unroll
        for (int c4 = 0; c4 < 8; c4++) {
            float4 qv[8], kv[8];
            #pragma unroll
            for (int d = 0; d < 8; d++) qv[d] = *(const float4*)(sQ + (ti + d*16)*QS + c4*4);
            #pragma unroll
            for (int d = 0; d < 8; d++) kv[d] = *(const float4*)(sK + (tj + d*16)*QS + c4*4);
            #pragma unroll
            for (int di = 0; di < 8; di++)
                #pragma unroll
                for (int dj = 0; dj < 8; dj++)
                    acc[di][dj] += qv[di].x*kv[dj].x + qv[di].y*kv[dj].y
                                 + qv[di].z*kv[dj].z + qv[di].w*kv[dj].w;
        }
        const float* mrow = mask + (size_t)win*16384;
        #pragma unroll
        for (int di = 0; di < 8; di++) {
            const int i = ti + di*16;
            #pragma unroll
            for (int dj = 0; dj < 8; dj++) {
                const int j = tj + dj*16;
                sA[i*AS + j] = acc[di][dj] + mrow[i*128 + j];
            }
        }
    }
    __syncthreads();

    // ---- pass 2: qr term. Thread owns row-pixel p (rows 2p,2p+1), 16 pj each.
    //      qr value is identical for columns 2pj and 2pj+1; embed row loaded once per pair.
    {
        const int p   = tid >> 2;
        const int pj0 = (tid & 3) << 4;
        const int phi = p >> 3, pwi = p & 7;
        const int i0  = 2*p;
        float4 q0[8], q1[8];
        #pragma unroll
        for (int c4 = 0; c4 < 8; c4++) {
            q0[c4] = *(const float4*)(sQ + i0*QS + c4*4);
            q1[c4] = *(const float4*)(sQ + (i0+1)*QS + c4*4);
        }
        #pragma unroll 4
        for (int pj = pj0; pj < pj0 + 16; pj++) {
            const int r = (phi - (pj >> 3) + 7)*15 + (pwi - (pj & 7) + 7);
            float s0 = 0.f, s1 = 0.f;
            #pragma unroll
            for (int c4 = 0; c4 < 8; c4++) {
                float4 e = *(const float4*)(sKE + r*QS + c4*4);
                s0 += q0[c4].x*e.x + q0[c4].y*e.y + q0[c4].z*e.z + q0[c4].w*e.w;
                s1 += q1[c4].x*e.x + q1[c4].y*e.y + q1[c4].z*e.z + q1[c4].w*e.w;
            }
            float2* d0 = (float2*)(sA + i0*AS + 2*pj);
            float2* d1 = (float2*)(sA + (i0+1)*AS + 2*pj);
            float2 t0 = *d0, t1 = *d1;
            t0.x += s0; t0.y += s0; *d0 = t0;
            t1.x += s1; t1.y += s1; *d1 = t1;
        }
    }
    __syncthreads();

    // ---- pass 3: kr term. Thread owns col-pixel p (cols 2p,2p+1), 16 pi each.
    //      kr value is identical for rows 2pi and 2pi+1; embed row loaded once per pair.
    {
        const int p   = tid >> 2;
        const int pi0 = (tid & 3) << 4;
        const int phj = p >> 3, pwj = p & 7;
        const int j0  = 2*p;
        float4 k0[8], k1[8];
        #pragma unroll
        for (int c4 = 0; c4 < 8; c4++) {
            k0[c4] = *(const float4*)(sK + j0*QS + c4*4);
            k1[c4] = *(const float4*)(sK + (j0+1)*QS + c4*4);
        }
        #pragma unroll 4
        for (int pi = pi0; pi < pi0 + 16; pi++) {
            const int r = ((pi >> 3) - phj + 7)*15 + ((pi & 7) - pwj + 7);
            float s0 = 0.f, s1 = 0.f;
            #pragma unroll
            for (int c4 = 0; c4 < 8; c4++) {
                float4 e = *(const float4*)(sQE + r*QS + c4*4);
                s0 += k0[c4].x*e.x + k0[c4].y*e.y + k0[c4].z*e.z + k0[c4].w*e.w;
                s1 += k1[c4].x*e.x + k1[c4].y*e.y + k1[c4].z*e.z + k1[c4].w*e.w;
            }
            float2* d0 = (float2*)(sA + (2*pi)*AS + j0);
            float2* d1 = (float2*)(sA + (2*pi+1)*AS + j0);
            float2 t0 = *d0, t1 = *d1;
            t0.x += s0; t0.y += s1; *d0 = t0;
            t1.x += s0; t1.y += s1; *d1 = t1;
        }
    }
    __syncthreads();

    // ---- softmax per row (warp per row, 16 rows per warp) ----
    {
        const int w = tid >> 5, l = tid & 31;
        for (int ii = 0; ii < 16; ii++) {
            const int i = w*16 + ii;
            float v[4];
            #pragma unroll
            for (int k = 0; k < 4; k++) v[k] = sA[i*AS + l + 32*k];
            float m = fmaxf(fmaxf(v[0], v[1]), fmaxf(v[2], v[3]));
            #pragma unroll
            for (int off = 16; off; off >>= 1) m = fmaxf(m, __shfl_xor_sync(0xffffffffu, m, off));
            float sum = 0.f;
            #pragma unroll
            for (int k = 0; k < 4; k++) { v[k] = __expf(v[k] - m); sum += v[k]; }
            #pragma unroll
            for (int off = 16; off; off >>= 1) sum += __shfl_xor_sync(0xffffffffu, sum, off);
            const float inv = 1.f / sum;
            #pragma unroll
            for (int k = 0; k < 4; k++) sA[i*AS + l + 32*k] = v[k]*inv;
        }
    }
    __syncthreads();

    // ---- AV + v_embed term + store.
    //      Thread owns row-pixel p (rows 2p,2p+1) x 8 channels; v/ve rows loaded once per pair.
    {
        const int p   = tid >> 2;
        const int c0  = (tid & 3) << 3;
        const int phi = p >> 3, pwi = p & 7;
        const int i0  = 2*p;
        float4 acc0a = {0,0,0,0}, acc0b = {0,0,0,0};
        float4 acc1a = {0,0,0,0}, acc1b = {0,0,0,0};

        #pragma unroll 4
        for (int pj = 0; pj < 64; pj++) {
            const float2 A0 = *(const float2*)(sA + i0*AS + 2*pj);
            const float2 A1 = *(const float2*)(sA + (i0+1)*AS + 2*pj);
            const float as0 = A0.x + A0.y;
            const float as1 = A1.x + A1.y;
            const int r = (phi - (pj >> 3) + 7)*15 + (pwi - (pj & 7) + 7);
            const float4 v0a = *(const float4*)(sV + (2*pj)*QS + c0);
            const float4 v0b = *(const float4*)(sV + (2*pj)*QS + c0 + 4);
            const float4 v1a = *(const float4*)(sV + (2*pj+1)*QS + c0);
            const float4 v1b = *(const float4*)(sV + (2*pj+1)*QS + c0 + 4);
            const float4 vea = *(const float4*)(sVE + r*QS + c0);
            const float4 veb = *(const float4*)(sVE + r*QS + c0 + 4);

            acc0a.x += A0.x*v0a.x + A0.y*v1a.x + as0*vea.x;
            acc0a.y += A0.x*v0a.y + A0.y*v1a.y + as0*vea.y;
            acc0a.z += A0.x*v0a.z + A0.y*v1a.z + as0*vea.z;
            acc0a.w += A0.x*v0a.w + A0.y*v1a.w + as0*vea.w;
            acc0b.x += A0.x*v0b.x + A0.y*v1b.x + as0*veb.x;
            acc0b.y += A0.x*v0b.y + A0.y*v1b.y + as0*veb.y;
            acc0b.z += A0.x*v0b.z + A0.y*v1b.z + as0*veb.z;
            acc0b.w += A0.x*v0b.w + A0.y*v1b.w + as0*veb.w;

            acc1a.x += A1.x*v0a.x + A1.y*v1a.x + as1*vea.x;
            acc1a.y += A1.x*v0a.y + A1.y*v1a.y + as1*vea.y;
            acc1a.z += A1.x*v0a.z + A1.y*v1a.z + as1*vea.z;
            acc1a.w += A1.x*v0a.w + A1.y*v1a.w + as1*vea.w;
            acc1b.x += A1.x*v0b.x + A1.y*v1b.x + as1*veb.x;
            acc1b.y += A1.x*v0b.y + A1.y*v1b.y + as1*veb.y;
            acc1b.z += A1.x*v0b.z + A1.y*v1b.z + as1*veb.z;
            acc1b.w += A1.x*v0b.w + A1.y*v1b.w + as1*veb.w;
        }

        const int wh = p >> 3, ww = p & 7;
        const int gy = (wi*8 + wh + SHIFT) & 127;
        const int gx = (wj*8 + ww + SHIFT) & 127;
        float* o0 = out + (size_t)(((b*128 + gy)*128 + gx)*2*128) + h*32 + c0;       // n=0
        float* o1 = o0 + 128;                                                         // n=1
        *(float4*)o0       = acc0a;
        *(float4*)(o0 + 4) = acc0b;
        *(float4*)o1       = acc1a;
        *(float4*)(o1 + 4) = acc1b;
    }
}

extern "C" void kernel_launch(void* const* d_in, const int* in_sizes, int n_in,
                              void* d_out, int out_size)
{
    const float* qkv  = (const float*)d_in[0];
    const float* mask = (const float*)d_in[1];
    const float* rpe  = (const float*)d_in[2];
    // d_in[3] (rel_pos_index) recomputed on the fly in-kernel

    const size_t smem = SMEM_FLOATS * sizeof(float);
    cudaFuncSetAttribute(swin_attn_kernel,
                         cudaFuncAttributeMaxDynamicSharedMemorySize, (int)smem);
    dim3 grid(1024, HEADS);
    swin_attn_kernel<<<grid, 256, smem>>>(qkv, mask, rpe, (float*)d_out);
}

// round 8
// speedup vs baseline: 1.0685x; 1.0685x over previous
#include <cuda_runtime.h>
#include <cuda_bf16.h>
#include <cstdint>

#define SHIFT 4
#define NR 225
#define AS 132          // fp32 attn row stride (floats, multiple of 4 for float4)
#define ES 36           // embed/OE fp32 row stride
#define SCALE 0.17677669529663687f

// smem byte offsets
#define SA_B   0         // fp32 attn 128x132            (67584)
#define QE_B   67584     // fp32 q_embed 225x36          (32400, pad 32768) -> AH overlay
#define KE_B   100352    // fp32 k_embed 225x36          (32400, pad 32768) -> OE overlay
#define VE_B   133120    // fp32 v_embed 225x36          (32400, pad 32768)
#define QH_B   165888    // bf16 q hi 128x20u32          (10240) -> AL overlay
#define QL_B   176128
#define KH_B   186368
#define KL_B   196608
#define VTH_B  206848    // bf16 V^T hi 32 x 68u32       (8704)
#define VTL_B  215552
#define SMEM_BYTES 224256
// overlays
#define AH_B   67584     // bf16 attn hi 128 x 68u32 (34816), valid after pass3
#define OE_B   102400    // fp32 embed partial 128x36 (18432), inside dead KE
#define AL_B   165888    // bf16 attn lo (34816), over dead QH..KL

__device__ __forceinline__ void mma_bf16(float* d, uint32_t a0, uint32_t a1, uint32_t a2, uint32_t a3,
                                         uint32_t b0, uint32_t b1) {
    asm volatile(
        "mma.sync.aligned.m16n8k16.row.col.f32.bf16.bf16.f32 "
        "{%0,%1,%2,%3},{%4,%5,%6,%7},{%8,%9},{%0,%1,%2,%3};"
        : "+f"(d[0]), "+f"(d[1]), "+f"(d[2]), "+f"(d[3])
        : "r"(a0), "r"(a1), "r"(a2), "r"(a3), "r"(b0), "r"(b1));
}
__device__ __forceinline__ uint32_t pkhi(float a, float b) {
    __nv_bfloat162 t = __floats2bfloat162_rn(a, b);
    return *reinterpret_cast<uint32_t*>(&t);
}
__device__ __forceinline__ uint32_t pklo(float a, float b) {
    float ha = __bfloat162float(__float2bfloat16(a));
    float hb = __bfloat162float(__float2bfloat16(b));
    __nv_bfloat162 t = __floats2bfloat162_rn(a - ha, b - hb);
    return *reinterpret_cast<uint32_t*>(&t);
}
__device__ __forceinline__ float2 rec2(uint32_t h, uint32_t l) {
    float2 a = __bfloat1622float2(*reinterpret_cast<__nv_bfloat162*>(&h));
    float2 b = __bfloat1622float2(*reinterpret_cast<__nv_bfloat162*>(&l));
    return make_float2(a.x + b.x, a.y + b.y);
}

__global__ __launch_bounds__(256, 1)
void swin_attn_kernel(const float* __restrict__ qkv,
                      const float* __restrict__ mask,
                      const float* __restrict__ rpe,
                      float* __restrict__ out)
{
    extern __shared__ char smc[];
    float* sA  = (float*)(smc + SA_B);
    float* sQE = (float*)(smc + QE_B);
    float* sKE = (float*)(smc + KE_B);
    float* sVE = (float*)(smc + VE_B);
    float* sOE = (float*)(smc + OE_B);
    uint32_t* QHu = (uint32_t*)(smc + QH_B);
    uint32_t* QLu = (uint32_t*)(smc + QL_B);
    uint32_t* KHu = (uint32_t*)(smc + KH_B);
    uint32_t* KLu = (uint32_t*)(smc + KL_B);
    uint32_t* AHu = (uint32_t*)(smc + AH_B);
    uint32_t* ALu = (uint32_t*)(smc + AL_B);
    uint32_t* VTHu = (uint32_t*)(smc + VTH_B);
    uint32_t* VTLu = (uint32_t*)(smc + VTL_B);

    const int tid = threadIdx.x, wid = tid >> 5, lane = tid & 31;
    const int h   = blockIdx.y;
    const int b   = blockIdx.x >> 8;
    const int win = blockIdx.x & 255;
    const int wi  = win >> 4, wj = win & 15;

    // ---- load q,k,v; emit q/k hi-lo bf16 (token-major) + V^T hi-lo ----
    {
        const int t = tid >> 1, half = tid & 1;
        const int wh = t >> 4, ww = (t >> 1) & 7, n = t & 1;
        const int gy = (wi*8 + wh + SHIFT) & 127;
        const int gx = (wj*8 + ww + SHIFT) & 127;
        const float* base = qkv + (size_t)((((b*128 + gy)*128 + gx)*2 + n)*384) + h*32 + half*16;
        #pragma unroll
        for (int c4 = 0; c4 < 4; c4++) {
            float4 q = ((const float4*)base)[c4];
            float4 k = ((const float4*)(base + 128))[c4];
            float4 v = ((const float4*)(base + 256))[c4];
            q.x *= SCALE; q.y *= SCALE; q.z *= SCALE; q.w *= SCALE;
            const int u = t*20 + half*8 + c4*2;
            QHu[u]   = pkhi(q.x, q.y); QHu[u+1] = pkhi(q.z, q.w);
            QLu[u]   = pklo(q.x, q.y); QLu[u+1] = pklo(q.z, q.w);
            KHu[u]   = pkhi(k.x, k.y); KHu[u+1] = pkhi(k.z, k.w);
            KLu[u]   = pklo(k.x, k.y); KLu[u+1] = pklo(k.z, k.w);
            float vv[4] = {v.x, v.y, v.z, v.w};
            #pragma unroll
            for (int e = 0; e < 4; e++) {
                const int c = half*16 + c4*4 + e;
                __nv_bfloat16 hi = __float2bfloat16(vv[e]);
                __nv_bfloat16 lo = __float2bfloat16(vv[e] - __bfloat162float(hi));
                ((__nv_bfloat16*)VTHu)[c*136 + t] = hi;
                ((__nv_bfloat16*)VTLu)[c*136 + t] = lo;
            }
        }
    }
    // ---- rel-pos tables (head-major row: q|k|v 32 each) ----
    for (int idx = tid; idx < NR*24; idx += 256) {
        const int r = idx / 24, s = idx % 24;
        const int sl = s >> 3, c4 = s & 7;
        float4 v = *(const float4*)(rpe + (size_t)r*384 + h*96 + sl*32 + c4*4);
        float* dst = (sl == 0) ? sQE : (sl == 1) ? sKE : sVE;
        if (sl == 0) { v.x *= SCALE; v.y *= SCALE; v.z *= SCALE; v.w *= SCALE; }
        *(float4*)(dst + r*ES + c4*4) = v;
    }
    __syncthreads();

    // ---- pass 1: qk via mma.sync (hi*hi + lo*hi + hi*lo), +mask -> sA ----
    {
        const int r0 = wid*16, r = lane >> 2, cq = lane & 3;
        uint32_t ah[2][4], al[2][4];
        #pragma unroll
        for (int kt = 0; kt < 2; kt++) {
            const int base0 = (r0 + r)*20 + kt*8 + cq;
            const int base1 = (r0 + r + 8)*20 + kt*8 + cq;
            ah[kt][0] = QHu[base0];     ah[kt][1] = QHu[base1];
            ah[kt][2] = QHu[base0 + 4]; ah[kt][3] = QHu[base1 + 4];
            al[kt][0] = QLu[base0];     al[kt][1] = QLu[base1];
            al[kt][2] = QLu[base0 + 4]; al[kt][3] = QLu[base1 + 4];
        }
        const float* mrow = mask + (size_t)win*16384;
        #pragma unroll
        for (int nt = 0; nt < 16; nt++) {
            float d[4] = {0.f, 0.f, 0.f, 0.f};
            #pragma unroll
            for (int kt = 0; kt < 2; kt++) {
                const int bidx = (nt*8 + r)*20 + kt*8 + cq;
                uint32_t bh0 = KHu[bidx], bh1 = KHu[bidx + 4];
                uint32_t bl0 = KLu[bidx], bl1 = KLu[bidx + 4];
                mma_bf16(d, ah[kt][0], ah[kt][1], ah[kt][2], ah[kt][3], bh0, bh1);
                mma_bf16(d, al[kt][0], al[kt][1], al[kt][2], al[kt][3], bh0, bh1);
                mma_bf16(d, ah[kt][0], ah[kt][1], ah[kt][2], ah[kt][3], bl0, bl1);
            }
            const int j0 = nt*8 + cq*2;
            const int i0 = r0 + r, i1 = r0 + r + 8;
            float2 m0 = *(const float2*)(mrow + i0*128 + j0);
            float2 m1 = *(const float2*)(mrow + i1*128 + j0);
            *(float2*)(sA + i0*AS + j0) = make_float2(d[0] + m0.x, d[1] + m0.y);
            *(float2*)(sA + i1*AS + j0) = make_float2(d[2] + m1.x, d[3] + m1.y);
        }
    }
    __syncthreads();

    // ---- pass 2: qr term (scalar, pixel-pair amortized; q rebuilt from hi+lo) ----
    {
        const int p = tid >> 2, pj0 = (tid & 3) << 4;
        const int phi = p >> 3, pwi = p & 7, i0 = 2*p;
        float4 q0[8], q1[8];
        #pragma unroll
        for (int c4 = 0; c4 < 8; c4++) {
            float2 xy = rec2(QHu[i0*20 + c4*2],     QLu[i0*20 + c4*2]);
            float2 zw = rec2(QHu[i0*20 + c4*2 + 1], QLu[i0*20 + c4*2 + 1]);
            q0[c4] = make_float4(xy.x, xy.y, zw.x, zw.y);
            xy = rec2(QHu[(i0+1)*20 + c4*2],     QLu[(i0+1)*20 + c4*2]);
            zw = rec2(QHu[(i0+1)*20 + c4*2 + 1], QLu[(i0+1)*20 + c4*2 + 1]);
            q1[c4] = make_float4(xy.x, xy.y, zw.x, zw.y);
        }
        #pragma unroll 4
        for (int pj = pj0; pj < pj0 + 16; pj++) {
            const int r = (phi - (pj >> 3) + 7)*15 + (pwi - (pj & 7) + 7);
            float s0 = 0.f, s1 = 0.f;
            #pragma unroll
            for (int c4 = 0; c4 < 8; c4++) {
                float4 e = *(const float4*)(sKE + r*ES + c4*4);
                s0 += q0[c4].x*e.x + q0[c4].y*e.y + q0[c4].z*e.z + q0[c4].w*e.w;
                s1 += q1[c4].x*e.x + q1[c4].y*e.y + q1[c4].z*e.z + q1[c4].w*e.w;
            }
            float2* d0 = (float2*)(sA + i0*AS + 2*pj);
            float2* d1 = (float2*)(sA + (i0+1)*AS + 2*pj);
            float2 t0 = *d0, t1 = *d1;
            t0.x += s0; t0.y += s0; *d0 = t0;
            t1.x += s1; t1.y += s1; *d1 = t1;
        }
    }
    __syncthreads();

    // ---- pass 3: kr term (k rebuilt from hi+lo) ----
    {
        const int p = tid >> 2, pi0 = (tid & 3) << 4;
        const int phj = p >> 3, pwj = p & 7, j0 = 2*p;
        float4 k0[8], k1[8];
        #pragma unroll
        for (int c4 = 0; c4 < 8; c4++) {
            float2 xy = rec2(KHu[j0*20 + c4*2],     KLu[j0*20 + c4*2]);
            float2 zw = rec2(KHu[j0*20 + c4*2 + 1], KLu[j0*20 + c4*2 + 1]);
            k0[c4] = make_float4(xy.x, xy.y, zw.x, zw.y);
            xy = rec2(KHu[(j0+1)*20 + c4*2],     KLu[(j0+1)*20 + c4*2]);
            zw = rec2(KHu[(j0+1)*20 + c4*2 + 1], KLu[(j0+1)*20 + c4*2 + 1]);
            k1[c4] = make_float4(xy.x, xy.y, zw.x, zw.y);
        }
        #pragma unroll 4
        for (int pi = pi0; pi < pi0 + 16; pi++) {
            const int r = ((pi >> 3) - phj + 7)*15 + ((pi & 7) - pwj + 7);
            float s0 = 0.f, s1 = 0.f;
            #pragma unroll
            for (int c4 = 0; c4 < 8; c4++) {
                float4 e = *(const float4*)(sQE + r*ES + c4*4);
                s0 += k0[c4].x*e.x + k0[c4].y*e.y + k0[c4].z*e.z + k0[c4].w*e.w;
                s1 += k1[c4].x*e.x + k1[c4].y*e.y + k1[c4].z*e.z + k1[c4].w*e.w;
            }
            float2* d0 = (float2*)(sA + (2*pi)*AS + j0);
            float2* d1 = (float2*)(sA + (2*pi+1)*AS + j0);
            float2 t0 = *d0, t1 = *d1;
            t0.x += s0; t0.y += s1; *d0 = t0;
            t1.x += s0; t1.y += s1; *d1 = t1;
        }
    }
    __syncthreads();

    // ---- softmax ----
    {
        const int w = tid >> 5, l = tid & 31;
        for (int ii = 0; ii < 16; ii++) {
            const int i = w*16 + ii;
            float v[4];
            #pragma unroll
            for (int k = 0; k < 4; k++) v[k] = sA[i*AS + l + 32*k];
            float m = fmaxf(fmaxf(v[0], v[1]), fmaxf(v[2], v[3]));
            #pragma unroll
            for (int off = 16; off; off >>= 1) m = fmaxf(m, __shfl_xor_sync(~0u, m, off));
            float s = 0.f;
            #pragma unroll
            for (int k = 0; k < 4; k++) { v[k] = __expf(v[k] - m); s += v[k]; }
            #pragma unroll
            for (int off = 16; off; off >>= 1) s += __shfl_xor_sync(~0u, s, off);
            const float inv = 1.f / s;
            #pragma unroll
            for (int k = 0; k < 4; k++) sA[i*AS + l + 32*k] = v[k]*inv;
        }
    }
    __syncthreads();

    // ---- emit attn hi/lo bf16 + scalar v_embed term -> sOE ----
    {
        const int i = tid >> 1, j0 = (tid & 1)*64;
        #pragma unroll 4
        for (int j = j0; j < j0 + 64; j += 4) {
            float4 a = *(const float4*)(sA + i*AS + j);
            uint2 hv, lv;
            hv.x = pkhi(a.x, a.y); hv.y = pkhi(a.z, a.w);
            lv.x = pklo(a.x, a.y); lv.y = pklo(a.z, a.w);
            *(uint2*)(AHu + i*68 + (j >> 1)) = hv;
            *(uint2*)(ALu + i*68 + (j >> 1)) = lv;
        }
    }
    {
        const int p = tid >> 2, c0 = (tid & 3) << 3;
        const int phi = p >> 3, pwi = p & 7, i0 = 2*p;
        float4 a0a = {0,0,0,0}, a0b = {0,0,0,0}, a1a = {0,0,0,0}, a1b = {0,0,0,0};
        #pragma unroll 4
        for (int pj = 0; pj < 64; pj++) {
            const float2 A0 = *(const float2*)(sA + i0*AS + 2*pj);
            const float2 A1 = *(const float2*)(sA + (i0+1)*AS + 2*pj);
            const float s0 = A0.x + A0.y, s1 = A1.x + A1.y;
            const int r = (phi - (pj >> 3) + 7)*15 + (pwi - (pj & 7) + 7);
            const float4 ea = *(const float4*)(sVE + r*ES + c0);
            const float4 eb = *(const float4*)(sVE + r*ES + c0 + 4);
            a0a.x += s0*ea.x; a0a.y += s0*ea.y; a0a.z += s0*ea.z; a0a.w += s0*ea.w;
            a0b.x += s0*eb.x; a0b.y += s0*eb.y; a0b.z += s0*eb.z; a0b.w += s0*eb.w;
            a1a.x += s1*ea.x; a1a.y += s1*ea.y; a1a.z += s1*ea.z; a1a.w += s1*ea.w;
            a1b.x += s1*eb.x; a1b.y += s1*eb.y; a1b.z += s1*eb.z; a1b.w += s1*eb.w;
        }
        *(float4*)(sOE + i0*ES + c0)         = a0a;
        *(float4*)(sOE + i0*ES + c0 + 4)     = a0b;
        *(float4*)(sOE + (i0+1)*ES + c0)     = a1a;
        *(float4*)(sOE + (i0+1)*ES + c0 + 4) = a1b;
    }
    __syncthreads();

    // ---- AV via mma.sync + add embed partial + store ----
    {
        const int r0 = wid*16, r = lane >> 2, cq = lane & 3;
        float d[4][4];
        #pragma unroll
        for (int nt = 0; nt < 4; nt++)
            #pragma unroll
            for (int e = 0; e < 4; e++) d[nt][e] = 0.f;
        #pragma unroll
        for (int kt = 0; kt < 8; kt++) {
            const int a0i = (r0 + r)*68 + kt*8 + cq;
            const int a1i = (r0 + r + 8)*68 + kt*8 + cq;
            uint32_t ah0 = AHu[a0i], ah1 = AHu[a1i], ah2 = AHu[a0i + 4], ah3 = AHu[a1i + 4];
            uint32_t al0 = ALu[a0i], al1 = ALu[a1i], al2 = ALu[a0i + 4], al3 = ALu[a1i + 4];
            #pragma unroll
            for (int nt = 0; nt < 4; nt++) {
                const int bidx = (nt*8 + r)*68 + kt*8 + cq;
                uint32_t bh0 = VTHu[bidx], bh1 = VTHu[bidx + 4];
                uint32_t bl0 = VTLu[bidx], bl1 = VTLu[bidx + 4];
                mma_bf16(d[nt], ah0, ah1, ah2, ah3, bh0, bh1);
                mma_bf16(d[nt], al0, al1, al2, al3, bh0, bh1);
                mma_bf16(d[nt], ah0, ah1, ah2, ah3, bl0, bl1);
            }
        }
        #pragma unroll
        for (int half = 0; half < 2; half++) {
            const int i = r0 + r + half*8;
            const int p = i >> 1, n = i & 1;
            const int gy = (wi*8 + (p >> 3) + SHIFT) & 127;
            const int gx = (wj*8 + (p & 7) + SHIFT) & 127;
            float* o = out + (size_t)((((b*128 + gy)*128 + gx)*2 + n)*128) + h*32;
            #pragma unroll
            for (int nt = 0; nt < 4; nt++) {
                const int j = nt*8 + cq*2;
                float2 e = *(const float2*)(sOE + i*ES + j);
                float2 rv;
                rv.x = d[nt][half*2 + 0] + e.x;
                rv.y = d[nt][half*2 + 1] + e.y;
                *(float2*)(o + j) = rv;
            }
        }
    }
}

extern "C" void kernel_launch(void* const* d_in, const int* in_sizes, int n_in,
                              void* d_out, int out_size)
{
    const float* qkv  = (const float*)d_in[0];
    const float* mask = (const float*)d_in[1];
    const float* rpe  = (const float*)d_in[2];
    cudaFuncSetAttribute(swin_attn_kernel,
                         cudaFuncAttributeMaxDynamicSharedMemorySize, SMEM_BYTES);
    dim3 grid(1024, 4);
    swin_attn_kernel<<<grid, 256, SMEM_BYTES>>>(qkv, mask, rpe, (float*)d_out);
}

// round 9
// speedup vs baseline: 1.1503x; 1.0765x over previous
#include <cuda_runtime.h>
#include <cuda_bf16.h>
#include <cstdint>

#define SHIFT 4
#define NR 225
#define AS 132          // fp32 attn row stride (floats, multiple of 4)
#define ES 36           // OE fp32 row stride
#define TS 40           // bf16 embed-table row stride (elements)
#define SCALE 0.17677669529663687f

// smem byte offsets
#define SA_B   0         // fp32 attn 128x132           (67584)
#define QEB_B  67584     // bf16 q_embed 225x40         (18432 pad)
#define KEB_B  86016     // bf16 k_embed 225x40
#define VEB_B  104448    // bf16 v_embed 225x40
#define QH_B   122880    // bf16 q hi 128x20u32         (10240)
#define QL_B   133120
#define KH_B   143360
#define KL_B   153600
#define VTH_B  163840    // bf16 V^T hi 32 x 68u32      (8704)
#define VTL_B  172544
#define OE_B   181248    // fp32 embed partial 128x36   (18432)
#define SMEM_BYTES 199680
// overlays
#define AH_B   67584     // bf16 attn hi 128x68u32 (34816) over dead QEb/KEb (after pass3)
#define AL_B   122880    // bf16 attn lo (34816) over dead QH..KL (after pass3)

__device__ __forceinline__ void mma_bf16(float* d, uint32_t a0, uint32_t a1, uint32_t a2, uint32_t a3,
                                         uint32_t b0, uint32_t b1) {
    asm volatile(
        "mma.sync.aligned.m16n8k16.row.col.f32.bf16.bf16.f32 "
        "{%0,%1,%2,%3},{%4,%5,%6,%7},{%8,%9},{%0,%1,%2,%3};"
        : "+f"(d[0]), "+f"(d[1]), "+f"(d[2]), "+f"(d[3])
        : "r"(a0), "r"(a1), "r"(a2), "r"(a3), "r"(b0), "r"(b1));
}
__device__ __forceinline__ uint32_t pkhi(float a, float b) {
    __nv_bfloat162 t = __floats2bfloat162_rn(a, b);
    return *reinterpret_cast<uint32_t*>(&t);
}
__device__ __forceinline__ uint32_t pklo(float a, float b) {
    float ha = __bfloat162float(__float2bfloat16(a));
    float hb = __bfloat162float(__float2bfloat16(b));
    __nv_bfloat162 t = __floats2bfloat162_rn(a - ha, b - hb);
    return *reinterpret_cast<uint32_t*>(&t);
}
__device__ __forceinline__ float2 rec2(uint32_t h, uint32_t l) {
    float2 a = __bfloat1622float2(*reinterpret_cast<__nv_bfloat162*>(&h));
    float2 b = __bfloat1622float2(*reinterpret_cast<__nv_bfloat162*>(&l));
    return make_float2(a.x + b.x, a.y + b.y);
}
__device__ __forceinline__ float2 upk(uint32_t h) {
    return __bfloat1622float2(*reinterpret_cast<__nv_bfloat162*>(&h));
}

__global__ __launch_bounds__(256, 1)
void swin_attn_kernel(const float* __restrict__ qkv,
                      const float* __restrict__ mask,
                      const float* __restrict__ rpe,
                      float* __restrict__ out)
{
    extern __shared__ char smc[];
    float* sA  = (float*)(smc + SA_B);
    __nv_bfloat16* QEb = (__nv_bfloat16*)(smc + QEB_B);
    __nv_bfloat16* KEb = (__nv_bfloat16*)(smc + KEB_B);
    __nv_bfloat16* VEb = (__nv_bfloat16*)(smc + VEB_B);
    float* sOE = (float*)(smc + OE_B);
    uint32_t* QHu = (uint32_t*)(smc + QH_B);
    uint32_t* QLu = (uint32_t*)(smc + QL_B);
    uint32_t* KHu = (uint32_t*)(smc + KH_B);
    uint32_t* KLu = (uint32_t*)(smc + KL_B);
    uint32_t* AHu = (uint32_t*)(smc + AH_B);
    uint32_t* ALu = (uint32_t*)(smc + AL_B);
    uint32_t* VTHu = (uint32_t*)(smc + VTH_B);
    uint32_t* VTLu = (uint32_t*)(smc + VTL_B);

    const int tid = threadIdx.x, wid = tid >> 5, lane = tid & 31;
    const int h   = blockIdx.y;
    const int b   = blockIdx.x >> 8;
    const int win = blockIdx.x & 255;
    const int wi  = win >> 4, wj = win & 15;

    // ---- load q,k,v; emit q/k hi-lo bf16 (token-major) + V^T hi-lo ----
    {
        const int t = tid >> 1, half = tid & 1;
        const int wh = t >> 4, ww = (t >> 1) & 7, n = t & 1;
        const int gy = (wi*8 + wh + SHIFT) & 127;
        const int gx = (wj*8 + ww + SHIFT) & 127;
        const float* base = qkv + (size_t)((((b*128 + gy)*128 + gx)*2 + n)*384) + h*32 + half*16;
        #pragma unroll
        for (int c4 = 0; c4 < 4; c4++) {
            float4 q = ((const float4*)base)[c4];
            float4 k = ((const float4*)(base + 128))[c4];
            float4 v = ((const float4*)(base + 256))[c4];
            q.x *= SCALE; q.y *= SCALE; q.z *= SCALE; q.w *= SCALE;
            const int u = t*20 + half*8 + c4*2;
            QHu[u]   = pkhi(q.x, q.y); QHu[u+1] = pkhi(q.z, q.w);
            QLu[u]   = pklo(q.x, q.y); QLu[u+1] = pklo(q.z, q.w);
            KHu[u]   = pkhi(k.x, k.y); KHu[u+1] = pkhi(k.z, k.w);
            KLu[u]   = pklo(k.x, k.y); KLu[u+1] = pklo(k.z, k.w);
            float vv[4] = {v.x, v.y, v.z, v.w};
            #pragma unroll
            for (int e = 0; e < 4; e++) {
                const int c = half*16 + c4*4 + e;
                __nv_bfloat16 hi = __float2bfloat16(vv[e]);
                __nv_bfloat16 lo = __float2bfloat16(vv[e] - __bfloat162float(hi));
                ((__nv_bfloat16*)VTHu)[c*136 + t] = hi;
                ((__nv_bfloat16*)VTLu)[c*136 + t] = lo;
            }
        }
    }
    // ---- rel-pos tables (head-major row: q|k|v 32 each) -> bf16 tables ----
    for (int idx = tid; idx < NR*24; idx += 256) {
        const int r = idx / 24, s = idx % 24;
        const int sl = s >> 3, c4 = s & 7;
        float4 v = *(const float4*)(rpe + (size_t)r*384 + h*96 + sl*32 + c4*4);
        __nv_bfloat16* dst = (sl == 0) ? QEb : (sl == 1) ? KEb : VEb;
        if (sl == 0) { v.x *= SCALE; v.y *= SCALE; v.z *= SCALE; v.w *= SCALE; }
        uint2 pk;
        pk.x = pkhi(v.x, v.y); pk.y = pkhi(v.z, v.w);
        *(uint2*)(dst + r*TS + c4*4) = pk;
    }
    __syncthreads();

    // ---- pass 1: qk via mma.sync (hi*hi + lo*hi + hi*lo), +mask -> sA ----
    {
        const int r0 = wid*16, r = lane >> 2, cq = lane & 3;
        uint32_t ah[2][4], al[2][4];
        #pragma unroll
        for (int kt = 0; kt < 2; kt++) {
            const int base0 = (r0 + r)*20 + kt*8 + cq;
            const int base1 = (r0 + r + 8)*20 + kt*8 + cq;
            ah[kt][0] = QHu[base0];     ah[kt][1] = QHu[base1];
            ah[kt][2] = QHu[base0 + 4]; ah[kt][3] = QHu[base1 + 4];
            al[kt][0] = QLu[base0];     al[kt][1] = QLu[base1];
            al[kt][2] = QLu[base0 + 4]; al[kt][3] = QLu[base1 + 4];
        }
        const float* mrow = mask + (size_t)win*16384;
        #pragma unroll
        for (int nt = 0; nt < 16; nt++) {
            float d[4] = {0.f, 0.f, 0.f, 0.f};
            #pragma unroll
            for (int kt = 0; kt < 2; kt++) {
                const int bidx = (nt*8 + r)*20 + kt*8 + cq;
                uint32_t bh0 = KHu[bidx], bh1 = KHu[bidx + 4];
                uint32_t bl0 = KLu[bidx], bl1 = KLu[bidx + 4];
                mma_bf16(d, ah[kt][0], ah[kt][1], ah[kt][2], ah[kt][3], bh0, bh1);
                mma_bf16(d, al[kt][0], al[kt][1], al[kt][2], al[kt][3], bh0, bh1);
                mma_bf16(d, ah[kt][0], ah[kt][1], ah[kt][2], ah[kt][3], bl0, bl1);
            }
            const int j0 = nt*8 + cq*2;
            const int i0 = r0 + r, i1 = r0 + r + 8;
            float2 m0 = *(const float2*)(mrow + i0*128 + j0);
            float2 m1 = *(const float2*)(mrow + i1*128 + j0);
            *(float2*)(sA + i0*AS + j0) = make_float2(d[0] + m0.x, d[1] + m0.y);
            *(float2*)(sA + i1*AS + j0) = make_float2(d[2] + m1.x, d[3] + m1.y);
        }
    }
    __syncthreads();

    // ---- pass 2: qr term (scalar, pair-amortized; bf16 k_embed table) ----
    {
        const int p = tid >> 2, pj0 = (tid & 3) << 4;
        const int phi = p >> 3, pwi = p & 7, i0 = 2*p;
        float4 q0[8], q1[8];
        #pragma unroll
        for (int c4 = 0; c4 < 8; c4++) {
            float2 xy = rec2(QHu[i0*20 + c4*2],     QLu[i0*20 + c4*2]);
            float2 zw = rec2(QHu[i0*20 + c4*2 + 1], QLu[i0*20 + c4*2 + 1]);
            q0[c4] = make_float4(xy.x, xy.y, zw.x, zw.y);
            xy = rec2(QHu[(i0+1)*20 + c4*2],     QLu[(i0+1)*20 + c4*2]);
            zw = rec2(QHu[(i0+1)*20 + c4*2 + 1], QLu[(i0+1)*20 + c4*2 + 1]);
            q1[c4] = make_float4(xy.x, xy.y, zw.x, zw.y);
        }
        #pragma unroll 4
        for (int pj = pj0; pj < pj0 + 16; pj++) {
            const int r = (phi - (pj >> 3) + 7)*15 + (pwi - (pj & 7) + 7);
            float s0 = 0.f, s1 = 0.f;
            #pragma unroll
            for (int c4 = 0; c4 < 8; c4++) {
                uint2 e = *(const uint2*)(KEb + r*TS + c4*4);
                float2 e01 = upk(e.x), e23 = upk(e.y);
                s0 += q0[c4].x*e01.x + q0[c4].y*e01.y + q0[c4].z*e23.x + q0[c4].w*e23.y;
                s1 += q1[c4].x*e01.x + q1[c4].y*e01.y + q1[c4].z*e23.x + q1[c4].w*e23.y;
            }
            float2* d0 = (float2*)(sA + i0*AS + 2*pj);
            float2* d1 = (float2*)(sA + (i0+1)*AS + 2*pj);
            float2 t0 = *d0, t1 = *d1;
            t0.x += s0; t0.y += s0; *d0 = t0;
            t1.x += s1; t1.y += s1; *d1 = t1;
        }
    }
    __syncthreads();

    // ---- pass 3: kr term (bf16 q_embed table) ----
    {
        const int p = tid >> 2, pi0 = (tid & 3) << 4;
        const int phj = p >> 3, pwj = p & 7, j0 = 2*p;
        float4 k0[8], k1[8];
        #pragma unroll
        for (int c4 = 0; c4 < 8; c4++) {
            float2 xy = rec2(KHu[j0*20 + c4*2],     KLu[j0*20 + c4*2]);
            float2 zw = rec2(KHu[j0*20 + c4*2 + 1], KLu[j0*20 + c4*2 + 1]);
            k0[c4] = make_float4(xy.x, xy.y, zw.x, zw.y);
            xy = rec2(KHu[(j0+1)*20 + c4*2],     KLu[(j0+1)*20 + c4*2]);
            zw = rec2(KHu[(j0+1)*20 + c4*2 + 1], KLu[(j0+1)*20 + c4*2 + 1]);
            k1[c4] = make_float4(xy.x, xy.y, zw.x, zw.y);
        }
        #pragma unroll 4
        for (int pi = pi0; pi < pi0 + 16; pi++) {
            const int r = ((pi >> 3) - phj + 7)*15 + ((pi & 7) - pwj + 7);
            float s0 = 0.f, s1 = 0.f;
            #pragma unroll
            for (int c4 = 0; c4 < 8; c4++) {
                uint2 e = *(const uint2*)(QEb + r*TS + c4*4);
                float2 e01 = upk(e.x), e23 = upk(e.y);
                s0 += k0[c4].x*e01.x + k0[c4].y*e01.y + k0[c4].z*e23.x + k0[c4].w*e23.y;
                s1 += k1[c4].x*e01.x + k1[c4].y*e01.y + k1[c4].z*e23.x + k1[c4].w*e23.y;
            }
            float2* d0 = (float2*)(sA + (2*pi)*AS + j0);
            float2* d1 = (float2*)(sA + (2*pi+1)*AS + j0);
            float2 t0 = *d0, t1 = *d1;
            t0.x += s0; t0.y += s1; *d0 = t0;
            t1.x += s0; t1.y += s1; *d1 = t1;
        }
    }
    __syncthreads();

    // ---- softmax ----
    {
        const int w = tid >> 5, l = tid & 31;
        for (int ii = 0; ii < 16; ii++) {
            const int i = w*16 + ii;
            float v[4];
            #pragma unroll
            for (int k = 0; k < 4; k++) v[k] = sA[i*AS + l + 32*k];
            float m = fmaxf(fmaxf(v[0], v[1]), fmaxf(v[2], v[3]));
            #pragma unroll
            for (int off = 16; off; off >>= 1) m = fmaxf(m, __shfl_xor_sync(~0u, m, off));
            float s = 0.f;
            #pragma unroll
            for (int k = 0; k < 4; k++) { v[k] = __expf(v[k] - m); s += v[k]; }
            #pragma unroll
            for (int off = 16; off; off >>= 1) s += __shfl_xor_sync(~0u, s, off);
            const float inv = 1.f / s;
            #pragma unroll
            for (int k = 0; k < 4; k++) sA[i*AS + l + 32*k] = v[k]*inv;
        }
    }
    __syncthreads();

    // ---- emit attn hi/lo bf16 + scalar v_embed term -> sOE ----
    {
        const int i = tid >> 1, j0 = (tid & 1)*64;
        #pragma unroll 4
        for (int j = j0; j < j0 + 64; j += 4) {
            float4 a = *(const float4*)(sA + i*AS + j);
            uint2 hv, lv;
            hv.x = pkhi(a.x, a.y); hv.y = pkhi(a.z, a.w);
            lv.x = pklo(a.x, a.y); lv.y = pklo(a.z, a.w);
            *(uint2*)(AHu + i*68 + (j >> 1)) = hv;
            *(uint2*)(ALu + i*68 + (j >> 1)) = lv;
        }
    }
    {
        const int p = tid >> 2, c0 = (tid & 3) << 3;
        const int phi = p >> 3, pwi = p & 7, i0 = 2*p;
        float4 a0a = {0,0,0,0}, a0b = {0,0,0,0}, a1a = {0,0,0,0}, a1b = {0,0,0,0};
        #pragma unroll 4
        for (int pj = 0; pj < 64; pj++) {
            const float2 A0 = *(const float2*)(sA + i0*AS + 2*pj);
            const float2 A1 = *(const float2*)(sA + (i0+1)*AS + 2*pj);
            const float s0 = A0.x + A0.y, s1 = A1.x + A1.y;
            const int r = (phi - (pj >> 3) + 7)*15 + (pwi - (pj & 7) + 7);
            uint2 ea = *(const uint2*)(VEb + r*TS + c0);
            uint2 eb = *(const uint2*)(VEb + r*TS + c0 + 4);
            float2 e0 = upk(ea.x), e1 = upk(ea.y), e2 = upk(eb.x), e3 = upk(eb.y);
            a0a.x += s0*e0.x; a0a.y += s0*e0.y; a0a.z += s0*e1.x; a0a.w += s0*e1.y;
            a0b.x += s0*e2.x; a0b.y += s0*e2.y; a0b.z += s0*e3.x; a0b.w += s0*e3.y;
            a1a.x += s1*e0.x; a1a.y += s1*e0.y; a1a.z += s1*e1.x; a1a.w += s1*e1.y;
            a1b.x += s1*e2.x; a1b.y += s1*e2.y; a1b.z += s1*e3.x; a1b.w += s1*e3.y;
        }
        *(float4*)(sOE + i0*ES + c0)         = a0a;
        *(float4*)(sOE + i0*ES + c0 + 4)     = a0b;
        *(float4*)(sOE + (i0+1)*ES + c0)     = a1a;
        *(float4*)(sOE + (i0+1)*ES + c0 + 4) = a1b;
    }
    __syncthreads();

    // ---- AV via mma.sync + add embed partial + store ----
    {
        const int r0 = wid*16, r = lane >> 2, cq = lane & 3;
        float d[4][4];
        #pragma unroll
        for (int nt = 0; nt < 4; nt++)
            #pragma unroll
            for (int e = 0; e < 4; e++) d[nt][e] = 0.f;
        #pragma unroll
        for (int kt = 0; kt < 8; kt++) {
            const int a0i = (r0 + r)*68 + kt*8 + cq;
            const int a1i = (r0 + r + 8)*68 + kt*8 + cq;
            uint32_t ah0 = AHu[a0i], ah1 = AHu[a1i], ah2 = AHu[a0i + 4], ah3 = AHu[a1i + 4];
            uint32_t al0 = ALu[a0i], al1 = ALu[a1i], al2 = ALu[a0i + 4], al3 = ALu[a1i + 4];
            #pragma unroll
            for (int nt = 0; nt < 4; nt++) {
                const int bidx = (nt*8 + r)*68 + kt*8 + cq;
                uint32_t bh0 = VTHu[bidx], bh1 = VTHu[bidx + 4];
                uint32_t bl0 = VTLu[bidx], bl1 = VTLu[bidx + 4];
                mma_bf16(d[nt], ah0, ah1, ah2, ah3, bh0, bh1);
                mma_bf16(d[nt], al0, al1, al2, al3, bh0, bh1);
                mma_bf16(d[nt], ah0, ah1, ah2, ah3, bl0, bl1);
            }
        }
        #pragma unroll
        for (int half = 0; half < 2; half++) {
            const int i = r0 + r + half*8;
            const int p = i >> 1, n = i & 1;
            const int gy = (wi*8 + (p >> 3) + SHIFT) & 127;
            const int gx = (wj*8 + (p & 7) + SHIFT) & 127;
            float* o = out + (size_t)((((b*128 + gy)*128 + gx)*2 + n)*128) + h*32;
            #pragma unroll
            for (int nt = 0; nt < 4; nt++) {
                const int j = nt*8 + cq*2;
                float2 e = *(const float2*)(sOE + i*ES + j);
                float2 rv;
                rv.x = d[nt][half*2 + 0] + e.x;
                rv.y = d[nt][half*2 + 1] + e.y;
                *(float2*)(o + j) = rv;
            }
        }
    }
}

extern "C" void kernel_launch(void* const* d_in, const int* in_sizes, int n_in,
                              void* d_out, int out_size)
{
    const float* qkv  = (const float*)d_in[0];
    const float* mask = (const float*)d_in[1];
    const float* rpe  = (const float*)d_in[2];
    cudaFuncSetAttribute(swin_attn_kernel,
                         cudaFuncAttributeMaxDynamicSharedMemorySize, SMEM_BYTES);
    dim3 grid(1024, 4);
    swin_attn_kernel<<<grid, 256, SMEM_BYTES>>>(qkv, mask, rpe, (float*)d_out);
}